// round 12
// baseline (speedup 1.0000x reference)
#include <cuda_runtime.h>
#include <cuda_fp16.h>
#include <math.h>
#include <stdint.h>

// Problem constants (fixed by the dataset)
constexpr int cB  = 128;
constexpr int cT  = 16;
constexpr int cF  = 256;
constexpr int cN  = 1024;
constexpr int cE  = 8192;
constexpr int cNC = 256;               // edge indices live in [0,256)
constexpr int M1   = cB * cNC;         // 32768 compact rows
constexpr int MX   = cB * cT;          // 2048 output rows
constexpr int MEXT = M1 + MX;          // 34816

// Output layout (flattened tuple, float32): mx | new_nodes | edges | weights | T+taus
constexpr long OFF_MX = 0;
constexpr long OFF_NN = (long)cB * cT * cF;
constexpr long OFF_ED = OFF_NN + (long)cB * cN * cF;
constexpr long OFF_WT = OFF_ED + (long)cB * 2 * cE;
constexpr long OFF_TT = OFF_WT + (long)cB * cE;

// hgemm smem (dynamic): double-buffered A[128x32] + B[256x32] half, stride 40
constexpr int HS_A    = 128 * 40;
constexpr int HS_B    = 256 * 40;
constexpr int SMEM_BYTES = 2 * (HS_A + HS_B) * 2;  // 61440 B

// k_agg smem: H batch slice 256x256 half
constexpr int AGG_SMEM = cNC * cF * 2;             // 131072 B

// Scratch (__device__ globals — no allocation allowed)
__device__ __half g_H  [(long)MEXT * cF];         // [compact nodes | X rows], half
__device__ __half g_AG [(long)MEXT * cF];         // sparse aggregation (X tail = 0)
__device__ __half g_h1 [(long)MEXT * cF];         // layer-1 hidden
__device__ __half g_F1 [(long)MX * cF];           // gathered h1 rows (layer-2 self term)
__device__ __half g_ag2[(long)MX * cF];           // layer-2 aggregation rows
__device__ __half g_WT [4][cF * cF];              // Ws1^T, Wm1^T, Ws2^T, Wm2^T (half)
__device__ int    g_cnt [cB * cNC];               // CSR: per-dst edge counts
__device__ int    g_off [cB * cNC];               // CSR: exclusive offsets
__device__ int    g_fill[cB * cNC];               // CSR: fill cursors
__device__ int2   g_csr [(long)cB * cE];          // CSR: (src, w-bits) per edge

// ---------------------------------------------------------------------------
// helpers
// ---------------------------------------------------------------------------
__device__ __forceinline__ void cpa16(void* s, const void* g) {
    unsigned sa = (unsigned)__cvta_generic_to_shared(s);
    asm volatile("cp.async.cg.shared.global [%0], [%1], 16;" :: "r"(sa), "l"(g));
}
__device__ __forceinline__ float fast_tanh(float x) {
    float ax = fabsf(x);
    float e;
    asm("ex2.approx.f32 %0, %1;" : "=f"(e) : "f"(ax * 2.8853900817779268f));
    float t = 1.0f - __fdividef(2.0f, e + 1.0f);
    return copysignf(t, x);
}
#define LDSM4(R, ADDR)                                                          \
    asm volatile("ldmatrix.sync.aligned.m8n8.x4.shared.b16 {%0,%1,%2,%3}, [%4];"\
                 : "=r"((R)[0]), "=r"((R)[1]), "=r"((R)[2]), "=r"((R)[3])       \
                 : "r"(ADDR))

// ---------------------------------------------------------------------------
// fp16 pipelined GEMM: D[Mx256] = [tanh]( A1@B1t [+ A2@B2t] )  (R8-proven)
// ---------------------------------------------------------------------------
__global__ __launch_bounds__(512, 1) void hgemm(
    const __half* __restrict__ A1, long sA,
    const __half* __restrict__ B1, long sB,
    const __half* __restrict__ A2, const __half* __restrict__ B2,
    void* __restrict__ Dp, long sD,
    int nseg, int out_half, int do_tanh)
{
    extern __shared__ __half sm[];
    __half* As[2] = { sm,            sm + HS_A };
    __half* Bs[2] = { sm + 2 * HS_A, sm + 2 * HS_A + HS_B };

    const int z = blockIdx.y;
    const __half* Ab[2]; Ab[0] = A1 + (long)z * sA; Ab[1] = A2 ? A2 + (long)z * sA : Ab[0];
    const __half* Bb[2]; Bb[0] = B1 + (long)z * sB; Bb[1] = B2 ? B2 : Bb[0];

    const long gm = (long)blockIdx.x * 128;
    const int tid = threadIdx.x, warp = tid >> 5, lane = tid & 31;
    const int g = lane >> 2, tg = lane & 3;
    const int wm = (warp & 1) * 64;
    const int wn = (warp >> 1) * 32;
    const int nkb = nseg * 8;
    const int arow = tid >> 2, acol = (tid & 3) * 8;

    unsigned aBase[2] = { (unsigned)__cvta_generic_to_shared(As[0]),
                          (unsigned)__cvta_generic_to_shared(As[1]) };
    unsigned bBase[2] = { (unsigned)__cvta_generic_to_shared(Bs[0]),
                          (unsigned)__cvta_generic_to_shared(Bs[1]) };
    int aoff[4], boff[2];
#pragma unroll
    for (int mi = 0; mi < 4; mi++)
        aoff[mi] = ((wm + mi * 16 + (lane & 15)) * 40 + (lane >> 4) * 8) * 2;
    {
        int q = lane >> 3, r = lane & 7;
#pragma unroll
        for (int pi = 0; pi < 2; pi++)
            boff[pi] = ((wn + pi * 16 + (q >> 1) * 8 + r) * 40 + (q & 1) * 8) * 2;
    }

    float acc[4][4][4];
#pragma unroll
    for (int a = 0; a < 4; a++)
#pragma unroll
        for (int b = 0; b < 4; b++)
#pragma unroll
            for (int c = 0; c < 4; c++) acc[a][b][c] = 0.f;

#define LOADK(KBI, BUF) do {                                                    \
    int seg_ = (KBI) >> 3, kk_ = ((KBI) & 7) * 32;                              \
    cpa16(&As[BUF][arow * 40 + acol], Ab[seg_] + (gm + arow) * 256 + kk_ + acol);\
    cpa16(&Bs[BUF][arow * 40 + acol], Bb[seg_] + (long)arow * 256 + kk_ + acol);\
    cpa16(&Bs[BUF][(arow + 128) * 40 + acol],                                   \
          Bb[seg_] + (long)(arow + 128) * 256 + kk_ + acol);                    \
    asm volatile("cp.async.commit_group;");                                     \
} while (0)

    LOADK(0, 0);
    for (int kb = 0; kb < nkb; kb++) {
        asm volatile("cp.async.wait_group 0;" ::: "memory");
        __syncthreads();
        if (kb + 1 < nkb) LOADK(kb + 1, (kb + 1) & 1);
        const int buf = kb & 1;
        const unsigned aB = aBase[buf], bB = bBase[buf];

#pragma unroll
        for (int ks = 0; ks < 2; ks++) {
            unsigned af[4][4], bf[2][4];
#pragma unroll
            for (int mi = 0; mi < 4; mi++) LDSM4(af[mi], aB + aoff[mi] + ks * 32);
#pragma unroll
            for (int pi = 0; pi < 2; pi++) LDSM4(bf[pi], bB + boff[pi] + ks * 32);
#pragma unroll
            for (int mi = 0; mi < 4; mi++)
#pragma unroll
                for (int ni = 0; ni < 4; ni++) {
                    unsigned b0 = bf[ni >> 1][(ni & 1) * 2];
                    unsigned b1 = bf[ni >> 1][(ni & 1) * 2 + 1];
                    asm volatile(
                        "mma.sync.aligned.m16n8k16.row.col.f32.f16.f16.f32 "
                        "{%0,%1,%2,%3},{%4,%5,%6,%7},{%8,%9},{%0,%1,%2,%3};"
                        : "+f"(acc[mi][ni][0]), "+f"(acc[mi][ni][1]),
                          "+f"(acc[mi][ni][2]), "+f"(acc[mi][ni][3])
                        : "r"(af[mi][0]), "r"(af[mi][1]), "r"(af[mi][2]), "r"(af[mi][3]),
                          "r"(b0), "r"(b1));
                }
        }
    }
#undef LOADK

    __half* Dh = (__half*)Dp + (long)z * sD;
    float*  Df = (float*) Dp + (long)z * sD;
#pragma unroll
    for (int mi = 0; mi < 4; mi++) {
        long r0 = gm + wm + mi * 16 + g;
#pragma unroll
        for (int ni = 0; ni < 4; ni++) {
            long c0 = wn + ni * 8 + tg * 2;
            float v0 = acc[mi][ni][0], v1 = acc[mi][ni][1];
            float v2 = acc[mi][ni][2], v3 = acc[mi][ni][3];
            if (do_tanh) {
                v0 = fast_tanh(v0); v1 = fast_tanh(v1);
                v2 = fast_tanh(v2); v3 = fast_tanh(v3);
            }
            if (out_half) {
                *(__half2*)&Dh[r0 * 256 + c0]       = __floats2half2_rn(v0, v1);
                *(__half2*)&Dh[(r0 + 8) * 256 + c0] = __floats2half2_rn(v2, v3);
            } else {
                Df[r0 * 256 + c0]           = v0;
                Df[r0 * 256 + c0 + 1]       = v1;
                Df[(r0 + 8) * 256 + c0]     = v2;
                Df[(r0 + 8) * 256 + c0 + 1] = v3;
            }
        }
    }
}

// ---------------------------------------------------------------------------
// Node passes
// ---------------------------------------------------------------------------
__global__ void k_nodes_compact(const float4* __restrict__ nodes, const float4* __restrict__ x,
                                const int* __restrict__ T, float4* __restrict__ out_nn) {
    const long total = (long)cB * cNC * 64;
    for (long idx = blockIdx.x * (long)blockDim.x + threadIdx.x; idx < total;
         idx += (long)gridDim.x * blockDim.x) {
        int b   = (int)(idx / (cNC * 64));
        int rem = (int)(idx - (long)b * (cNC * 64));
        int n = rem >> 6, q = rem & 63;
        int d = n - T[b];
        float4 v = (d >= 0 && d < cT) ? x[((long)b * cT + d) * 64 + q]
                                      : nodes[((long)b * cN + n) * 64 + q];
        out_nn[((long)b * cN + n) * 64 + q] = v;
        __half2* hp = (__half2*)&g_H[((long)b * cNC + n) * cF + q * 4];
        hp[0] = __floats2half2_rn(v.x, v.y);
        hp[1] = __floats2half2_rn(v.z, v.w);
    }
}

__global__ void k_nodes_rest(const float4* __restrict__ x, const float4* __restrict__ nodes,
                             const int* __restrict__ T, float4* __restrict__ out_nn) {
    const long total = (long)cB * (cN - cNC) * 64;
    for (long idx = blockIdx.x * (long)blockDim.x + threadIdx.x; idx < total;
         idx += (long)gridDim.x * blockDim.x) {
        int b   = (int)(idx / ((cN - cNC) * 64));
        int rem = (int)(idx - (long)b * ((cN - cNC) * 64));
        int n = cNC + (rem >> 6), q = rem & 63;
        int d = n - T[b];
        long o = ((long)b * cN + n) * 64 + q;
        out_nn[o] = (d >= 0 && d < cT) ? x[((long)b * cT + d) * 64 + q] : nodes[o];
    }
}

// X rows of g_H = cast(x); matching tail rows of g_AG = 0
__global__ void k_xtail(const float2* __restrict__ x) {
    const long total = (long)MX * cF / 2;
    __half2* hH = (__half2*)&g_H[(long)M1 * cF];
    __half2* hA = (__half2*)&g_AG[(long)M1 * cF];
    for (long i = blockIdx.x * (long)blockDim.x + threadIdx.x; i < total;
         i += (long)gridDim.x * blockDim.x) {
        float2 v = x[i];
        hH[i] = __floats2half2_rn(v.x, v.y);
        hA[i] = __floats2half2_rn(0.f, 0.f);
    }
}

__global__ void k_zcnt(void) {
    int i = blockIdx.x * blockDim.x + threadIdx.x;
    if (i < cB * cNC) { g_cnt[i] = 0; g_fill[i] = 0; }
}

// edges pass A: passthrough out_ed/out_wt + per-dst counts
__global__ void k_cntA(const int* __restrict__ edges, const float* __restrict__ w,
                       float* __restrict__ out_ed, float* __restrict__ out_wt) {
    const int total = cB * cE;
    for (int i = blockIdx.x * blockDim.x + threadIdx.x; i < total; i += gridDim.x * blockDim.x) {
        int b = i / cE, e = i - b * cE;
        int s = edges[(long)b * 2 * cE + e];
        int d = edges[(long)b * 2 * cE + cE + e];
        float wv = w[i];
        out_ed[(long)b * 2 * cE + e]      = (float)s;
        out_ed[(long)b * 2 * cE + cE + e] = (float)d;
        out_wt[i] = wv;
        if (s >= 0 && d >= 0 && s < cNC && d < cNC)
            atomicAdd(&g_cnt[b * cNC + d], 1);
    }
}

// per-batch exclusive scan of counts (+ T+taus output)
__global__ __launch_bounds__(256) void k_scan(const int* __restrict__ T,
                                              const int* __restrict__ taus,
                                              float* __restrict__ out_tt) {
    __shared__ int s[cNC];
    int b = blockIdx.x, t = threadIdx.x;
    int c = g_cnt[b * cNC + t];
    s[t] = c;
    __syncthreads();
    for (int off = 1; off < cNC; off <<= 1) {
        int v = (t >= off) ? s[t - off] : 0;
        __syncthreads();
        s[t] += v;
        __syncthreads();
    }
    g_off[b * cNC + t] = s[t] - c;   // exclusive
    if (t == 0) out_tt[b] = (float)(T[b] + taus[b]);
}

// edges pass B: fill CSR lists
__global__ void k_fillB(const int* __restrict__ edges, const float* __restrict__ w) {
    const int total = cB * cE;
    for (int i = blockIdx.x * blockDim.x + threadIdx.x; i < total; i += gridDim.x * blockDim.x) {
        int b = i / cE, e = i - b * cE;
        int s = edges[(long)b * 2 * cE + e];
        int d = edges[(long)b * 2 * cE + cE + e];
        if (s >= 0 && d >= 0 && s < cNC && d < cNC) {
            int pos = g_off[b * cNC + d] + atomicAdd(&g_fill[b * cNC + d], 1);
            g_csr[(long)b * cE + pos] = make_int2(s, __float_as_int(w[i]));
        }
    }
}

// sparse aggregation: AGG[b][d] = sum_{edges->d} w * H[b][src]   (fp32 acc)
// one CTA per batch; H slice in smem; warp per dst; lane covers 8 feats.
__global__ __launch_bounds__(256, 1) void k_agg(void) {
    extern __shared__ __half Hs[];
    const int b = blockIdx.x;
    const int tid = threadIdx.x, warp = tid >> 5, lane = tid & 31;

    const __half* Hb = g_H + (long)b * cNC * cF;
#pragma unroll 8
    for (int u = tid; u < cNC * cF / 8; u += 256)
        cpa16((char*)Hs + u * 16, (const char*)Hb + u * 16);
    asm volatile("cp.async.commit_group;");
    asm volatile("cp.async.wait_group 0;" ::: "memory");
    __syncthreads();

    const int2* cb = g_csr + (long)b * cE;
    __half* AGb = g_AG + (long)b * cNC * cF;

    for (int d = warp; d < cNC; d += 8) {
        const int o = g_off[b * cNC + d];
        const int n = g_cnt[b * cNC + d];
        float acc[8] = {0, 0, 0, 0, 0, 0, 0, 0};
        for (int j0 = 0; j0 < n; j0 += 32) {
            int2 e = (j0 + lane < n) ? cb[o + j0 + lane] : make_int2(0, 0);
            int m = min(32, n - j0);
            for (int j = 0; j < m; j++) {
                int   src = __shfl_sync(0xffffffffu, e.x, j);
                float wv  = __int_as_float(__shfl_sync(0xffffffffu, e.y, j));
                uint4 hv = *(const uint4*)&Hs[src * cF + lane * 8];
                float2 f0 = __half22float2(*(__half2*)&hv.x);
                float2 f1 = __half22float2(*(__half2*)&hv.y);
                float2 f2 = __half22float2(*(__half2*)&hv.z);
                float2 f3 = __half22float2(*(__half2*)&hv.w);
                acc[0] += wv * f0.x; acc[1] += wv * f0.y;
                acc[2] += wv * f1.x; acc[3] += wv * f1.y;
                acc[4] += wv * f2.x; acc[5] += wv * f2.y;
                acc[6] += wv * f3.x; acc[7] += wv * f3.y;
            }
        }
        uint4 outv;
        *(__half2*)&outv.x = __floats2half2_rn(acc[0], acc[1]);
        *(__half2*)&outv.y = __floats2half2_rn(acc[2], acc[3]);
        *(__half2*)&outv.z = __floats2half2_rn(acc[4], acc[5]);
        *(__half2*)&outv.w = __floats2half2_rn(acc[6], acc[7]);
        *(uint4*)&AGb[d * cF + lane * 8] = outv;
    }
}

// layer-2: agg rows via CSR (dst in [T, T+16)) + self-row gather
__global__ __launch_bounds__(256) void k_aggpack2(const int* __restrict__ T) {
    const int b = blockIdx.x;
    const int tid = threadIdx.x, warp = tid >> 5, lane = tid & 31;
    const int Tb = T[b];
    const int2* cb = g_csr + (long)b * cE;

    for (int r = warp; r < cT; r += 8) {
        const int row = Tb + r;
        const long jrow = (long)b * cT + r;
        float acc[8] = {0, 0, 0, 0, 0, 0, 0, 0};
        const __half* f1src;
        if (row < cNC) {
            const int o = g_off[b * cNC + row];
            const int n = g_cnt[b * cNC + row];
            for (int j0 = 0; j0 < n; j0 += 32) {
                int2 e = (j0 + lane < n) ? cb[o + j0 + lane] : make_int2(0, 0);
                int m = min(32, n - j0);
                for (int j = 0; j < m; j++) {
                    int   src = __shfl_sync(0xffffffffu, e.x, j);
                    float wv  = __int_as_float(__shfl_sync(0xffffffffu, e.y, j));
                    uint4 hv = *(const uint4*)&g_h1[((long)b * cNC + src) * cF + lane * 8];
                    float2 f0 = __half22float2(*(__half2*)&hv.x);
                    float2 f1 = __half22float2(*(__half2*)&hv.y);
                    float2 f2 = __half22float2(*(__half2*)&hv.z);
                    float2 f3 = __half22float2(*(__half2*)&hv.w);
                    acc[0] += wv * f0.x; acc[1] += wv * f0.y;
                    acc[2] += wv * f1.x; acc[3] += wv * f1.y;
                    acc[4] += wv * f2.x; acc[5] += wv * f2.y;
                    acc[6] += wv * f3.x; acc[7] += wv * f3.y;
                }
            }
            f1src = &g_h1[((long)b * cNC + row) * cF];
        } else {
            f1src = &g_h1[((long)M1 + jrow) * cF];
        }
        uint4 outv;
        *(__half2*)&outv.x = __floats2half2_rn(acc[0], acc[1]);
        *(__half2*)&outv.y = __floats2half2_rn(acc[2], acc[3]);
        *(__half2*)&outv.z = __floats2half2_rn(acc[4], acc[5]);
        *(__half2*)&outv.w = __floats2half2_rn(acc[6], acc[7]);
        *(uint4*)&g_ag2[jrow * cF + lane * 8] = outv;
        *(uint4*)&g_F1[jrow * cF + lane * 8]  = *(const uint4*)&f1src[lane * 8];
    }
}

// pack weights transposed to half: g_WT[z][n][k] = W_z[k][n]
__global__ void k_packWT(const float* __restrict__ W0, const float* __restrict__ W1,
                         const float* __restrict__ W2, const float* __restrict__ W3) {
    __shared__ float t[32][33];
    const float* Ws[4] = {W0, W1, W2, W3};
    int z = blockIdx.z;
    int x0 = blockIdx.x * 32, y0 = blockIdx.y * 32;
    int tx = threadIdx.x, ty = threadIdx.y;
#pragma unroll
    for (int i = 0; i < 4; i++)
        t[ty + i * 8][tx] = Ws[z][(y0 + ty + i * 8) * cF + x0 + tx];
    __syncthreads();
#pragma unroll
    for (int i = 0; i < 4; i++)
        g_WT[z][(x0 + ty + i * 8) * cF + y0 + tx] = __float2half(t[tx][ty + i * 8]);
}

// ---------------------------------------------------------------------------
// Launcher
// ---------------------------------------------------------------------------
extern "C" void kernel_launch(void* const* d_in, const int* in_sizes, int n_in,
                              void* d_out, int out_size) {
    const float* x       = (const float*)d_in[0];
    const int*   taus    = (const int*)  d_in[1];
    const float* nodes   = (const float*)d_in[2];
    const int*   edges   = (const int*)  d_in[3];
    const float* weights = (const float*)d_in[4];
    const int*   T       = (const int*)  d_in[5];
    const float* Ws1     = (const float*)d_in[6];
    const float* Wm1     = (const float*)d_in[7];
    const float* Ws2     = (const float*)d_in[8];
    const float* Wm2     = (const float*)d_in[9];

    float* out    = (float*)d_out;
    float* out_mx = out + OFF_MX;
    float* out_nn = out + OFF_NN;
    float* out_ed = out + OFF_ED;
    float* out_wt = out + OFF_WT;
    float* out_tt = out + OFF_TT;

    __half *p_H, *p_AG, *p_h1, *p_F1, *p_ag2;
    __half (*p_WT)[cF * cF];
    cudaGetSymbolAddress((void**)&p_H,    g_H);
    cudaGetSymbolAddress((void**)&p_AG,   g_AG);
    cudaGetSymbolAddress((void**)&p_h1,   g_h1);
    cudaGetSymbolAddress((void**)&p_F1,   g_F1);
    cudaGetSymbolAddress((void**)&p_ag2,  g_ag2);
    cudaGetSymbolAddress((void**)&p_WT,   g_WT);

    static cudaStream_t s1 = nullptr, s2 = nullptr;
    static cudaEvent_t evF = nullptr, ev1 = nullptr, evC = nullptr, evX = nullptr;
    if (!s1) {
        cudaStreamCreateWithFlags(&s1, cudaStreamNonBlocking);
        cudaStreamCreateWithFlags(&s2, cudaStreamNonBlocking);
        cudaEventCreateWithFlags(&evF, cudaEventDisableTiming);
        cudaEventCreateWithFlags(&ev1, cudaEventDisableTiming);
        cudaEventCreateWithFlags(&evC, cudaEventDisableTiming);
        cudaEventCreateWithFlags(&evX, cudaEventDisableTiming);
        cudaFuncSetAttribute(hgemm, cudaFuncAttributeMaxDynamicSharedMemorySize, SMEM_BYTES);
        cudaFuncSetAttribute(k_agg, cudaFuncAttributeMaxDynamicSharedMemorySize, AGG_SMEM);
    }

    // fork
    cudaEventRecord(evF, 0);
    cudaStreamWaitEvent(s1, evF, 0);
    cudaStreamWaitEvent(s2, evF, 0);

    // s1: bulk passthrough (DRAM-bound; overlaps all compute)
    k_nodes_rest<<<4096, 256, 0, s1>>>((const float4*)x, (const float4*)nodes, T,
                                       (float4*)out_nn);
    cudaEventRecord(ev1, s1);

    // s2: staging — compact node pass, X/AG tails, packed weights
    k_nodes_compact<<<2048, 256, 0, s2>>>((const float4*)nodes, (const float4*)x, T,
                                          (float4*)out_nn);
    cudaEventRecord(evC, s2);                      // g_H compact ready
    k_xtail<<<512, 256, 0, s2>>>((const float2*)x);
    k_packWT<<<dim3(8, 8, 4), dim3(32, 8), 0, s2>>>(Ws1, Wm1, Ws2, Wm2);
    cudaEventRecord(evX, s2);                      // g_H X rows + AG tail + WT ready

    // main: CSR build fused with edges/weights passthrough
    k_zcnt<<<cB, 256>>>();
    k_cntA<<<2048, 256>>>(edges, weights, out_ed, out_wt);
    k_scan<<<cB, 256>>>(T, taus, out_tt);
    k_fillB<<<2048, 256>>>(edges, weights);

    // sparse aggregation (CUDA-core, smem-resident H)
    cudaStreamWaitEvent(0, evC, 0);
    k_agg<<<cB, 256, AGG_SMEM>>>();

    // G_1: h1 = tanh(Hext @ Ws1 + AGext @ Wm1)   (M=34816, K=512)
    cudaStreamWaitEvent(0, evX, 0);
    hgemm<<<dim3(MEXT / 128, 1), 512, SMEM_BYTES>>>(
        p_H, 0,
        p_WT[0], 0,
        p_AG, p_WT[1],
        p_h1, 0,
        2, 1, 1);

    // layer-2 aggregation rows + self-row gather (CSR)
    k_aggpack2<<<cB, 256>>>(T);

    // G_2: mx = tanh(F1 @ Ws2 + ag2 @ Wm2)   (M=2048, K=512)
    hgemm<<<dim3(MX / 128, 1), 512, SMEM_BYTES>>>(
        p_F1, 0,
        p_WT[2], 0,
        p_ag2, p_WT[3],
        out_mx, 0,
        2, 0, 1);

    // join passthrough branch
    cudaStreamWaitEvent(0, ev1, 0);
}

// round 13
// speedup vs baseline: 1.1999x; 1.1999x over previous
#include <cuda_runtime.h>
#include <cuda_fp16.h>
#include <math.h>
#include <stdint.h>

// Problem constants (fixed by the dataset)
constexpr int cB  = 128;
constexpr int cT  = 16;
constexpr int cF  = 256;
constexpr int cN  = 1024;
constexpr int cE  = 8192;
constexpr int cNC = 256;               // edge indices live in [0,256)
constexpr int M1   = cB * cNC;         // 32768 compact rows
constexpr int MX   = cB * cT;          // 2048 output rows
constexpr int MEXT = M1 + MX;          // 34816

// Output layout (flattened tuple, float32): mx | new_nodes | edges | weights | T+taus
constexpr long OFF_MX = 0;
constexpr long OFF_NN = (long)cB * cT * cF;
constexpr long OFF_ED = OFF_NN + (long)cB * cN * cF;
constexpr long OFF_WT = OFF_ED + (long)cB * 2 * cE;
constexpr long OFF_TT = OFF_WT + (long)cB * cE;

// stage tile sizes (halves), stride-40 layout
constexpr int FS_A = 128 * 40;                     // 5120
constexpr int FS_B = 256 * 40;                     // 10240
// hgemm (G_2): double-buffered A+B
constexpr int SMEM_BYTES = 2 * (FS_A + FS_B) * 2;  // 61440 B
// k_layer1: A dbl + B dbl + 8 AH chunks (each 128x40)
constexpr int FSMEM_BYTES = (2 * FS_A + 2 * FS_B + 8 * FS_A) * 2;  // 143360 B

// Scratch (__device__ globals — no allocation allowed)
__device__ __half g_adjh[(long)cB * cNC * cNC];   // half adjacency (atomic build)
__device__ __half g_H  [(long)MEXT * cF];         // [compact nodes | X rows], half
__device__ __half g_HT [(long)cB * cNC * cF];     // per-batch transposed H [feat][node]
__device__ __half g_h1 [(long)MEXT * cF];         // layer-1 hidden
__device__ __half g_F1 [(long)MX * cF];           // gathered h1 rows (layer-2 self term)
__device__ __half g_ag2[(long)MX * cF];           // layer-2 aggregation rows
__device__ __half g_WT [4][cF * cF];              // Ws1^T, Wm1^T, Ws2^T, Wm2^T (half)

// ---------------------------------------------------------------------------
// helpers
// ---------------------------------------------------------------------------
__device__ __forceinline__ void cpa16(void* s, const void* g) {
    unsigned sa = (unsigned)__cvta_generic_to_shared(s);
    asm volatile("cp.async.cg.shared.global [%0], [%1], 16;" :: "r"(sa), "l"(g));
}
__device__ __forceinline__ float fast_tanh(float x) {
    float ax = fabsf(x);
    float e;
    asm("ex2.approx.f32 %0, %1;" : "=f"(e) : "f"(ax * 2.8853900817779268f));
    float t = 1.0f - __fdividef(2.0f, e + 1.0f);
    return copysignf(t, x);
}
#define LDSM4(R, ADDR)                                                          \
    asm volatile("ldmatrix.sync.aligned.m8n8.x4.shared.b16 {%0,%1,%2,%3}, [%4];"\
                 : "=r"((R)[0]), "=r"((R)[1]), "=r"((R)[2]), "=r"((R)[3])       \
                 : "r"(ADDR))
#define MMA16(ACC, AF, B0, B1)                                                  \
    asm volatile("mma.sync.aligned.m16n8k16.row.col.f32.f16.f16.f32 "           \
                 "{%0,%1,%2,%3},{%4,%5,%6,%7},{%8,%9},{%0,%1,%2,%3};"           \
                 : "+f"((ACC)[0]), "+f"((ACC)[1]), "+f"((ACC)[2]), "+f"((ACC)[3])\
                 : "r"((AF)[0]), "r"((AF)[1]), "r"((AF)[2]), "r"((AF)[3]),      \
                   "r"(B0), "r"(B1))

// compute one 32-wide k-slab (2 ldmatrix slices) from smem bases aB/bB
#define COMPUTE_SLAB(aB, bB)                                                    \
    _Pragma("unroll")                                                           \
    for (int ks = 0; ks < 2; ks++) {                                            \
        unsigned af[4][4], bf[2][4];                                            \
        _Pragma("unroll")                                                       \
        for (int mi = 0; mi < 4; mi++) LDSM4(af[mi], (aB) + aoff[mi] + ks * 32);\
        _Pragma("unroll")                                                       \
        for (int pi = 0; pi < 2; pi++) LDSM4(bf[pi], (bB) + boff[pi] + ks * 32);\
        _Pragma("unroll")                                                       \
        for (int mi = 0; mi < 4; mi++)                                          \
            _Pragma("unroll")                                                   \
            for (int ni = 0; ni < 4; ni++)                                      \
                MMA16(acc[mi][ni], af[mi],                                      \
                      bf[ni >> 1][(ni & 1) * 2], bf[ni >> 1][(ni & 1) * 2 + 1]);\
    }

// ---------------------------------------------------------------------------
// k_layer1: fused (AH = Adj@H) + (h1 = tanh(H@Ws1 + AH@Wm1)), 272 CTAs.
// bx < 256: compact tile (batch bx>>1, half bx&1) — phase1 + phase2(K=512).
// bx >= 256: X rows — phase2 seg0 only (agg = 0).
// ---------------------------------------------------------------------------
__global__ __launch_bounds__(512, 1) void k_layer1(void) {
    extern __shared__ __half sm[];
    __half* As[2] = { sm,            sm + FS_A };
    __half* Bs[2] = { sm + 2 * FS_A, sm + 2 * FS_A + FS_B };
    __half* AH    = sm + 2 * FS_A + 2 * FS_B;

    const int bx = blockIdx.x;
    const bool compact = bx < 2 * cB;
    const int tid = threadIdx.x, warp = tid >> 5, lane = tid & 31;
    const int g = lane >> 2, tg = lane & 3;
    const int wm = (warp & 1) * 64;
    const int wn = (warp >> 1) * 32;
    const int arow = tid >> 2, acol = (tid & 3) * 8;

    unsigned aBase[2] = { (unsigned)__cvta_generic_to_shared(As[0]),
                          (unsigned)__cvta_generic_to_shared(As[1]) };
    unsigned bBase[2] = { (unsigned)__cvta_generic_to_shared(Bs[0]),
                          (unsigned)__cvta_generic_to_shared(Bs[1]) };
    unsigned ahBase = (unsigned)__cvta_generic_to_shared(AH);

    int aoff[4], boff[2];
#pragma unroll
    for (int mi = 0; mi < 4; mi++)
        aoff[mi] = ((wm + mi * 16 + (lane & 15)) * 40 + (lane >> 4) * 8) * 2;
    {
        int q = lane >> 3, r = lane & 7;
#pragma unroll
        for (int pi = 0; pi < 2; pi++)
            boff[pi] = ((wn + pi * 16 + (q >> 1) * 8 + r) * 40 + (q & 1) * 8) * 2;
    }

    float acc[4][4][4];
#pragma unroll
    for (int a = 0; a < 4; a++)
#pragma unroll
        for (int b = 0; b < 4; b++)
#pragma unroll
            for (int c = 0; c < 4; c++) acc[a][b][c] = 0.f;

    const __half* Hrow = g_H + (long)bx * 128 * cF;   // this tile's H rows

    if (compact) {
        // ---- phase 1: AH tile = Adj rows @ H (B operand = per-batch HT) ----
        const __half* adjA = g_adjh + (long)bx * 128 * cNC;
        const __half* HTb  = g_HT + (long)(bx >> 1) * cNC * cF;

#define LOAD1(KBI, BUF) do {                                                    \
    int kk_ = (KBI) * 32;                                                       \
    cpa16(&As[BUF][arow * 40 + acol], adjA + (long)arow * cNC + kk_ + acol);    \
    cpa16(&Bs[BUF][arow * 40 + acol], HTb + (long)arow * cF + kk_ + acol);      \
    cpa16(&Bs[BUF][(arow + 128) * 40 + acol],                                   \
          HTb + (long)(arow + 128) * cF + kk_ + acol);                          \
    asm volatile("cp.async.commit_group;");                                     \
} while (0)

        LOAD1(0, 0);
        for (int kb = 0; kb < 8; kb++) {
            asm volatile("cp.async.wait_group 0;" ::: "memory");
            __syncthreads();
            if (kb + 1 < 8) LOAD1(kb + 1, (kb + 1) & 1);
            COMPUTE_SLAB(aBase[kb & 1], bBase[kb & 1]);
        }
#undef LOAD1

        // store AH tile to smem chunks (stage layout: chunk k = cols [32k,32k+32))
#pragma unroll
        for (int mi = 0; mi < 4; mi++) {
            int r0 = wm + mi * 16 + g;
#pragma unroll
            for (int ni = 0; ni < 4; ni++) {
                int c0 = wn + ni * 8 + tg * 2;
                __half* chp = AH + (c0 >> 5) * FS_A + (c0 & 31);
                *(__half2*)&chp[r0 * 40] =
                    __floats2half2_rn(acc[mi][ni][0], acc[mi][ni][1]);
                *(__half2*)&chp[(r0 + 8) * 40] =
                    __floats2half2_rn(acc[mi][ni][2], acc[mi][ni][3]);
                acc[mi][ni][0] = acc[mi][ni][1] = acc[mi][ni][2] = acc[mi][ni][3] = 0.f;
            }
        }
        __syncthreads();
    }

    // ---- phase 2: h1 = tanh(H @ Ws1 [+ AH @ Wm1]) ----
    const int nkb2 = compact ? 16 : 8;

#define LOAD2(KBI, BUF) do {                                                    \
    int kk_ = ((KBI) & 7) * 32;                                                 \
    if ((KBI) < 8)                                                              \
        cpa16(&As[BUF][arow * 40 + acol], Hrow + (long)arow * cF + kk_ + acol); \
    const __half* Wt_ = ((KBI) < 8) ? g_WT[0] : g_WT[1];                        \
    cpa16(&Bs[BUF][arow * 40 + acol], Wt_ + (long)arow * cF + kk_ + acol);      \
    cpa16(&Bs[BUF][(arow + 128) * 40 + acol],                                   \
          Wt_ + (long)(arow + 128) * cF + kk_ + acol);                          \
    asm volatile("cp.async.commit_group;");                                     \
} while (0)

    LOAD2(0, 0);
    for (int kb = 0; kb < nkb2; kb++) {
        asm volatile("cp.async.wait_group 0;" ::: "memory");
        __syncthreads();
        if (kb + 1 < nkb2) LOAD2(kb + 1, (kb + 1) & 1);
        unsigned aB = (kb < 8) ? aBase[kb & 1]
                               : (ahBase + (unsigned)(kb - 8) * (FS_A * 2));
        COMPUTE_SLAB(aB, bBase[kb & 1]);
    }
#undef LOAD2

    __half* Dh = g_h1 + (long)bx * 128 * cF;
#pragma unroll
    for (int mi = 0; mi < 4; mi++) {
        int r0 = wm + mi * 16 + g;
#pragma unroll
        for (int ni = 0; ni < 4; ni++) {
            int c0 = wn + ni * 8 + tg * 2;
            *(__half2*)&Dh[(long)r0 * cF + c0] = __floats2half2_rn(
                fast_tanh(acc[mi][ni][0]), fast_tanh(acc[mi][ni][1]));
            *(__half2*)&Dh[(long)(r0 + 8) * cF + c0] = __floats2half2_rn(
                fast_tanh(acc[mi][ni][2]), fast_tanh(acc[mi][ni][3]));
        }
    }
}

// ---------------------------------------------------------------------------
// hgemm (R8-proven): D[Mx256] = [tanh]( A1@B1t [+ A2@B2t] ) — used for G_2
// ---------------------------------------------------------------------------
__global__ __launch_bounds__(512, 1) void hgemm(
    const __half* __restrict__ A1, long sA,
    const __half* __restrict__ B1, long sB,
    const __half* __restrict__ A2, const __half* __restrict__ B2,
    void* __restrict__ Dp, long sD,
    int nseg, int out_half, int do_tanh)
{
    extern __shared__ __half sm[];
    __half* As[2] = { sm,            sm + FS_A };
    __half* Bs[2] = { sm + 2 * FS_A, sm + 2 * FS_A + FS_B };

    const int z = blockIdx.y;
    const __half* Ab[2]; Ab[0] = A1 + (long)z * sA; Ab[1] = A2 ? A2 + (long)z * sA : Ab[0];
    const __half* Bb[2]; Bb[0] = B1 + (long)z * sB; Bb[1] = B2 ? B2 : Bb[0];

    const long gm = (long)blockIdx.x * 128;
    const int tid = threadIdx.x, warp = tid >> 5, lane = tid & 31;
    const int g = lane >> 2, tg = lane & 3;
    const int wm = (warp & 1) * 64;
    const int wn = (warp >> 1) * 32;
    const int nkb = nseg * 8;
    const int arow = tid >> 2, acol = (tid & 3) * 8;

    unsigned aBase[2] = { (unsigned)__cvta_generic_to_shared(As[0]),
                          (unsigned)__cvta_generic_to_shared(As[1]) };
    unsigned bBase[2] = { (unsigned)__cvta_generic_to_shared(Bs[0]),
                          (unsigned)__cvta_generic_to_shared(Bs[1]) };
    int aoff[4], boff[2];
#pragma unroll
    for (int mi = 0; mi < 4; mi++)
        aoff[mi] = ((wm + mi * 16 + (lane & 15)) * 40 + (lane >> 4) * 8) * 2;
    {
        int q = lane >> 3, r = lane & 7;
#pragma unroll
        for (int pi = 0; pi < 2; pi++)
            boff[pi] = ((wn + pi * 16 + (q >> 1) * 8 + r) * 40 + (q & 1) * 8) * 2;
    }

    float acc[4][4][4];
#pragma unroll
    for (int a = 0; a < 4; a++)
#pragma unroll
        for (int b = 0; b < 4; b++)
#pragma unroll
            for (int c = 0; c < 4; c++) acc[a][b][c] = 0.f;

#define LOADK(KBI, BUF) do {                                                    \
    int seg_ = (KBI) >> 3, kk_ = ((KBI) & 7) * 32;                              \
    cpa16(&As[BUF][arow * 40 + acol], Ab[seg_] + (gm + arow) * 256 + kk_ + acol);\
    cpa16(&Bs[BUF][arow * 40 + acol], Bb[seg_] + (long)arow * 256 + kk_ + acol);\
    cpa16(&Bs[BUF][(arow + 128) * 40 + acol],                                   \
          Bb[seg_] + (long)(arow + 128) * 256 + kk_ + acol);                    \
    asm volatile("cp.async.commit_group;");                                     \
} while (0)

    LOADK(0, 0);
    for (int kb = 0; kb < nkb; kb++) {
        asm volatile("cp.async.wait_group 0;" ::: "memory");
        __syncthreads();
        if (kb + 1 < nkb) LOADK(kb + 1, (kb + 1) & 1);
        COMPUTE_SLAB(aBase[kb & 1], bBase[kb & 1]);
    }
#undef LOADK

    __half* Dh = (__half*)Dp + (long)z * sD;
    float*  Df = (float*) Dp + (long)z * sD;
#pragma unroll
    for (int mi = 0; mi < 4; mi++) {
        long r0 = gm + wm + mi * 16 + g;
#pragma unroll
        for (int ni = 0; ni < 4; ni++) {
            long c0 = wn + ni * 8 + tg * 2;
            float v0 = acc[mi][ni][0], v1 = acc[mi][ni][1];
            float v2 = acc[mi][ni][2], v3 = acc[mi][ni][3];
            if (do_tanh) {
                v0 = fast_tanh(v0); v1 = fast_tanh(v1);
                v2 = fast_tanh(v2); v3 = fast_tanh(v3);
            }
            if (out_half) {
                *(__half2*)&Dh[r0 * 256 + c0]       = __floats2half2_rn(v0, v1);
                *(__half2*)&Dh[(r0 + 8) * 256 + c0] = __floats2half2_rn(v2, v3);
            } else {
                Df[r0 * 256 + c0]           = v0;
                Df[r0 * 256 + c0 + 1]       = v1;
                Df[(r0 + 8) * 256 + c0]     = v2;
                Df[(r0 + 8) * 256 + c0 + 1] = v3;
            }
        }
    }
}

// ---------------------------------------------------------------------------
// staging / passthrough kernels (R8-proven)
// ---------------------------------------------------------------------------
__global__ void k_nodes_compactT(const float* __restrict__ nodes, const float* __restrict__ x,
                                 const int* __restrict__ T, float* __restrict__ out_nn) {
    __shared__ __half t[32][33];
    int b = blockIdx.z;
    int x0 = blockIdx.x * 32, y0 = blockIdx.y * 32;   // x0: feat, y0: node
    int tx = threadIdx.x, ty = threadIdx.y;
    int Tb = T[b];
#pragma unroll
    for (int i = 0; i < 4; i++) {
        int n = y0 + ty + i * 8;
        int d = n - Tb;
        float v = (d >= 0 && d < cT) ? x[((long)b * cT + d) * cF + x0 + tx]
                                     : nodes[((long)b * cN + n) * cF + x0 + tx];
        out_nn[((long)b * cN + n) * cF + x0 + tx] = v;
        __half h = __float2half(v);
        g_H[((long)b * cNC + n) * cF + x0 + tx] = h;
        t[ty + i * 8][tx] = h;
    }
    __syncthreads();
#pragma unroll
    for (int i = 0; i < 4; i++)
        g_HT[((long)b * cNC + x0 + ty + i * 8) * cF + y0 + tx] = t[tx][ty + i * 8];
}

__global__ void k_nodes_rest(const float4* __restrict__ x, const float4* __restrict__ nodes,
                             const int* __restrict__ T, float4* __restrict__ out_nn) {
    const long total = (long)cB * (cN - cNC) * 64;
    for (long idx = blockIdx.x * (long)blockDim.x + threadIdx.x; idx < total;
         idx += (long)gridDim.x * blockDim.x) {
        int b   = (int)(idx / ((cN - cNC) * 64));
        int rem = (int)(idx - (long)b * ((cN - cNC) * 64));
        int n = cNC + (rem >> 6), q = rem & 63;
        int d = n - T[b];
        long o = ((long)b * cN + n) * 64 + q;
        out_nn[o] = (d >= 0 && d < cT) ? x[((long)b * cT + d) * 64 + q] : nodes[o];
    }
}

__global__ void k_castx(const float2* __restrict__ x) {
    const long total = (long)MX * cF / 2;
    for (long i = blockIdx.x * (long)blockDim.x + threadIdx.x; i < total;
         i += (long)gridDim.x * blockDim.x) {
        float2 v = x[i];
        *(__half2*)&g_H[(long)M1 * cF + i * 2] = __floats2half2_rn(v.x, v.y);
    }
}

__global__ void k_zero4(float4* p, long n4) {
    for (long i = blockIdx.x * (long)blockDim.x + threadIdx.x; i < n4;
         i += (long)gridDim.x * blockDim.x)
        p[i] = make_float4(0.f, 0.f, 0.f, 0.f);
}

// Fused edge pass: out_ed/out_wt/out_tt passthrough + half adjacency atomics
__global__ void k_edges_fused(const int* __restrict__ edges, const float* __restrict__ w,
                              const int* __restrict__ T, const int* __restrict__ taus,
                              float* __restrict__ out_ed, float* __restrict__ out_wt,
                              float* __restrict__ out_tt) {
    if (blockIdx.x == 0 && threadIdx.x < cB)
        out_tt[threadIdx.x] = (float)(T[threadIdx.x] + taus[threadIdx.x]);
    const int total = cB * cE;
    for (int i = blockIdx.x * blockDim.x + threadIdx.x; i < total; i += gridDim.x * blockDim.x) {
        int b = i / cE, e = i - b * cE;
        int s = edges[(long)b * 2 * cE + e];
        int d = edges[(long)b * 2 * cE + cE + e];
        float wv = w[i];
        out_ed[(long)b * 2 * cE + e]      = (float)s;
        out_ed[(long)b * 2 * cE + cE + e] = (float)d;
        out_wt[i] = wv;
        if (s >= 0 && d >= 0 && s < cNC && d < cNC)
            atomicAdd(&g_adjh[((long)b * cNC + d) * cNC + s], __float2half(wv));
    }
}

__global__ void k_packWT(const float* __restrict__ W0, const float* __restrict__ W1,
                         const float* __restrict__ W2, const float* __restrict__ W3) {
    __shared__ float t[32][33];
    const float* Ws[4] = {W0, W1, W2, W3};
    int z = blockIdx.z;
    int x0 = blockIdx.x * 32, y0 = blockIdx.y * 32;
    int tx = threadIdx.x, ty = threadIdx.y;
#pragma unroll
    for (int i = 0; i < 4; i++)
        t[ty + i * 8][tx] = Ws[z][(y0 + ty + i * 8) * cF + x0 + tx];
    __syncthreads();
#pragma unroll
    for (int i = 0; i < 4; i++)
        g_WT[z][(x0 + ty + i * 8) * cF + y0 + tx] = __float2half(t[tx][ty + i * 8]);
}

// layer-2 aggregation rows + gather self rows: one CTA per batch
__global__ __launch_bounds__(256) void k_aggpack(const int* __restrict__ T) {
    __shared__ float adj_sm[cT][cNC];
    const int b = blockIdx.x;
    const int c = threadIdx.x;
    const int Tb = T[b];

#pragma unroll
    for (int r = 0; r < cT; r++) {
        int row = Tb + r;
        adj_sm[r][c] = (row < cNC)
            ? __half2float(g_adjh[((long)b * cNC + row) * cNC + c]) : 0.f;
    }
    __syncthreads();

    float acc[cT];
#pragma unroll
    for (int r = 0; r < cT; r++) acc[r] = 0.f;

    const __half* h1b = g_h1 + (long)b * cNC * cF;
#pragma unroll 4
    for (int s = 0; s < cNC; s++) {
        float v = __half2float(h1b[(long)s * cF + c]);
#pragma unroll
        for (int r = 0; r < cT; r++) acc[r] += adj_sm[r][s] * v;
    }

#pragma unroll
    for (int r = 0; r < cT; r++) {
        int row = Tb + r;
        long j = (long)b * cT + r;
        g_ag2[j * cF + c] = __float2half(acc[r]);
        g_F1[j * cF + c] = (row < cNC) ? g_h1[((long)b * cNC + row) * cF + c]
                                       : g_h1[((long)M1 + j) * cF + c];
    }
}

// ---------------------------------------------------------------------------
// Launcher
// ---------------------------------------------------------------------------
extern "C" void kernel_launch(void* const* d_in, const int* in_sizes, int n_in,
                              void* d_out, int out_size) {
    const float* x       = (const float*)d_in[0];
    const int*   taus    = (const int*)  d_in[1];
    const float* nodes   = (const float*)d_in[2];
    const int*   edges   = (const int*)  d_in[3];
    const float* weights = (const float*)d_in[4];
    const int*   T       = (const int*)  d_in[5];
    const float* Ws1     = (const float*)d_in[6];
    const float* Wm1     = (const float*)d_in[7];
    const float* Ws2     = (const float*)d_in[8];
    const float* Wm2     = (const float*)d_in[9];

    float* out    = (float*)d_out;
    float* out_mx = out + OFF_MX;
    float* out_nn = out + OFF_NN;
    float* out_ed = out + OFF_ED;
    float* out_wt = out + OFF_WT;
    float* out_tt = out + OFF_TT;

    __half *p_adjh, *p_F1, *p_ag2;
    __half (*p_WT)[cF * cF];
    cudaGetSymbolAddress((void**)&p_adjh, g_adjh);
    cudaGetSymbolAddress((void**)&p_F1,   g_F1);
    cudaGetSymbolAddress((void**)&p_ag2,  g_ag2);
    cudaGetSymbolAddress((void**)&p_WT,   g_WT);

    static cudaStream_t s1 = nullptr, s2 = nullptr;
    static cudaEvent_t evF = nullptr, ev1 = nullptr, evX = nullptr;
    if (!s1) {
        cudaStreamCreateWithFlags(&s1, cudaStreamNonBlocking);
        cudaStreamCreateWithFlags(&s2, cudaStreamNonBlocking);
        cudaEventCreateWithFlags(&evF, cudaEventDisableTiming);
        cudaEventCreateWithFlags(&ev1, cudaEventDisableTiming);
        cudaEventCreateWithFlags(&evX, cudaEventDisableTiming);
        cudaFuncSetAttribute(hgemm, cudaFuncAttributeMaxDynamicSharedMemorySize, SMEM_BYTES);
        cudaFuncSetAttribute(k_layer1, cudaFuncAttributeMaxDynamicSharedMemorySize, FSMEM_BYTES);
    }

    // fork
    cudaEventRecord(evF, 0);
    cudaStreamWaitEvent(s1, evF, 0);
    cudaStreamWaitEvent(s2, evF, 0);

    // s1: bulk passthrough (DRAM-bound, overlaps all compute)
    k_nodes_rest<<<4096, 256, 0, s1>>>((const float4*)x, (const float4*)nodes, T,
                                       (float4*)out_nn);
    cudaEventRecord(ev1, s1);

    // s2: staging — compact nodes (out_nn + H + HT), X rows, packed weights
    k_nodes_compactT<<<dim3(8, 8, cB), dim3(32, 8), 0, s2>>>(nodes, x, T, out_nn);
    k_castx<<<512, 256, 0, s2>>>((const float2*)x);
    k_packWT<<<dim3(8, 8, 4), dim3(32, 8), 0, s2>>>(Ws1, Wm1, Ws2, Wm2);
    cudaEventRecord(evX, s2);

    // main: adjacency (half atomics) fused with edges/weights/tt passthrough
    k_zero4<<<1024, 256>>>((float4*)p_adjh, (long)cB * cNC * cNC / 8);
    k_edges_fused<<<2048, 256>>>(edges, weights, T, taus, out_ed, out_wt, out_tt);
    cudaStreamWaitEvent(0, evX, 0);

    // fused layer 1: AH (smem) + h1 = tanh(H@Ws1 + AH@Wm1), one launch
    k_layer1<<<MEXT / 128, 512, FSMEM_BYTES>>>();

    // layer-2 aggregation rows + self-row gather
    k_aggpack<<<cB, 256>>>(T);

    // G_2: mx = tanh(F1 @ Ws2 + ag2 @ Wm2)   (M=2048, K=512, fp32 out)
    hgemm<<<dim3(MX / 128, 1), 512, SMEM_BYTES>>>(
        p_F1, 0,
        p_WT[2], 0,
        p_ag2, p_WT[3],
        out_mx, 0,
        2, 0, 1);

    // join passthrough branch
    cudaStreamWaitEvent(0, ev1, 0);
}

// round 14
// speedup vs baseline: 1.2892x; 1.0744x over previous
#include <cuda_runtime.h>
#include <cuda_fp16.h>
#include <math.h>
#include <stdint.h>

// Problem constants (fixed by the dataset)
constexpr int cB  = 128;
constexpr int cT  = 16;
constexpr int cF  = 256;
constexpr int cN  = 1024;
constexpr int cE  = 8192;
constexpr int cNC = 256;               // edge indices live in [0,256)
constexpr int M1   = cB * cNC;         // 32768 compact rows
constexpr int MX   = cB * cT;          // 2048 output rows
constexpr int MEXT = M1 + MX;          // 34816

// Output layout (flattened tuple, float32): mx | new_nodes | edges | weights | T+taus
constexpr long OFF_MX = 0;
constexpr long OFF_NN = (long)cB * cT * cF;
constexpr long OFF_ED = OFF_NN + (long)cB * cN * cF;
constexpr long OFF_WT = OFF_ED + (long)cB * 2 * cE;
constexpr long OFF_TT = OFF_WT + (long)cB * cE;

// stage tile sizes (halves), stride-40 layout
constexpr int FS_A = 128 * 40;                     // 5120
constexpr int FS_B = 256 * 40;                     // 10240
// k_layer1: A dbl + B dbl + 8 AH chunks (each 128x40)
constexpr int FSMEM_BYTES = (2 * FS_A + 2 * FS_B + 8 * FS_A) * 2;  // 143360 B
// k_layer2: adj fp32 [16][256] + F 16 chunks [16][40] + B dbl [256][40]
constexpr int L2_ADJ = cT * cNC * 4;               // 16384 B
constexpr int L2_F   = 16 * (cT * 40) * 2;         // 20480 B
constexpr int L2SMEM_BYTES = L2_ADJ + L2_F + 2 * FS_B * 2;  // 77824 B

// Scratch (__device__ globals — no allocation allowed)
__device__ __half g_adjh[(long)cB * cNC * cNC];   // half adjacency (atomic build)
__device__ __half g_H  [(long)MEXT * cF];         // [compact nodes | X rows], half
__device__ __half g_HT [(long)cB * cNC * cF];     // per-batch transposed H [feat][node]
__device__ __half g_h1 [(long)MEXT * cF];         // layer-1 hidden
__device__ __half g_WT [4][cF * cF];              // Ws1^T, Wm1^T, Ws2^T, Wm2^T (half)

// ---------------------------------------------------------------------------
// helpers
// ---------------------------------------------------------------------------
__device__ __forceinline__ void cpa16(void* s, const void* g) {
    unsigned sa = (unsigned)__cvta_generic_to_shared(s);
    asm volatile("cp.async.cg.shared.global [%0], [%1], 16;" :: "r"(sa), "l"(g));
}
__device__ __forceinline__ float fast_tanh(float x) {
    float ax = fabsf(x);
    float e;
    asm("ex2.approx.f32 %0, %1;" : "=f"(e) : "f"(ax * 2.8853900817779268f));
    float t = 1.0f - __fdividef(2.0f, e + 1.0f);
    return copysignf(t, x);
}
#define LDSM4(R, ADDR)                                                          \
    asm volatile("ldmatrix.sync.aligned.m8n8.x4.shared.b16 {%0,%1,%2,%3}, [%4];"\
                 : "=r"((R)[0]), "=r"((R)[1]), "=r"((R)[2]), "=r"((R)[3])       \
                 : "r"(ADDR))
#define MMA16(ACC, AF, B0, B1)                                                  \
    asm volatile("mma.sync.aligned.m16n8k16.row.col.f32.f16.f16.f32 "           \
                 "{%0,%1,%2,%3},{%4,%5,%6,%7},{%8,%9},{%0,%1,%2,%3};"           \
                 : "+f"((ACC)[0]), "+f"((ACC)[1]), "+f"((ACC)[2]), "+f"((ACC)[3])\
                 : "r"((AF)[0]), "r"((AF)[1]), "r"((AF)[2]), "r"((AF)[3]),      \
                   "r"(B0), "r"(B1))

// compute one 32-wide k-slab (2 ldmatrix slices) from smem bases aB/bB
#define COMPUTE_SLAB(aB, bB)                                                    \
    _Pragma("unroll")                                                           \
    for (int ks = 0; ks < 2; ks++) {                                            \
        unsigned af[4][4], bf[2][4];                                            \
        _Pragma("unroll")                                                       \
        for (int mi = 0; mi < 4; mi++) LDSM4(af[mi], (aB) + aoff[mi] + ks * 32);\
        _Pragma("unroll")                                                       \
        for (int pi = 0; pi < 2; pi++) LDSM4(bf[pi], (bB) + boff[pi] + ks * 32);\
        _Pragma("unroll")                                                       \
        for (int mi = 0; mi < 4; mi++)                                          \
            _Pragma("unroll")                                                   \
            for (int ni = 0; ni < 4; ni++)                                      \
                MMA16(acc[mi][ni], af[mi],                                      \
                      bf[ni >> 1][(ni & 1) * 2], bf[ni >> 1][(ni & 1) * 2 + 1]);\
    }

// ---------------------------------------------------------------------------
// k_layer1: fused (AH = Adj@H) + (h1 = tanh(H@Ws1 + AH@Wm1)), 272 CTAs.
// (R13-proven)
// ---------------------------------------------------------------------------
__global__ __launch_bounds__(512, 1) void k_layer1(void) {
    extern __shared__ __half sm[];
    __half* As[2] = { sm,            sm + FS_A };
    __half* Bs[2] = { sm + 2 * FS_A, sm + 2 * FS_A + FS_B };
    __half* AH    = sm + 2 * FS_A + 2 * FS_B;

    const int bx = blockIdx.x;
    const bool compact = bx < 2 * cB;
    const int tid = threadIdx.x, warp = tid >> 5, lane = tid & 31;
    const int g = lane >> 2, tg = lane & 3;
    const int wm = (warp & 1) * 64;
    const int wn = (warp >> 1) * 32;
    const int arow = tid >> 2, acol = (tid & 3) * 8;

    unsigned aBase[2] = { (unsigned)__cvta_generic_to_shared(As[0]),
                          (unsigned)__cvta_generic_to_shared(As[1]) };
    unsigned bBase[2] = { (unsigned)__cvta_generic_to_shared(Bs[0]),
                          (unsigned)__cvta_generic_to_shared(Bs[1]) };
    unsigned ahBase = (unsigned)__cvta_generic_to_shared(AH);

    int aoff[4], boff[2];
#pragma unroll
    for (int mi = 0; mi < 4; mi++)
        aoff[mi] = ((wm + mi * 16 + (lane & 15)) * 40 + (lane >> 4) * 8) * 2;
    {
        int q = lane >> 3, r = lane & 7;
#pragma unroll
        for (int pi = 0; pi < 2; pi++)
            boff[pi] = ((wn + pi * 16 + (q >> 1) * 8 + r) * 40 + (q & 1) * 8) * 2;
    }

    float acc[4][4][4];
#pragma unroll
    for (int a = 0; a < 4; a++)
#pragma unroll
        for (int b = 0; b < 4; b++)
#pragma unroll
            for (int c = 0; c < 4; c++) acc[a][b][c] = 0.f;

    const __half* Hrow = g_H + (long)bx * 128 * cF;

    if (compact) {
        const __half* adjA = g_adjh + (long)bx * 128 * cNC;
        const __half* HTb  = g_HT + (long)(bx >> 1) * cNC * cF;

#define LOAD1(KBI, BUF) do {                                                    \
    int kk_ = (KBI) * 32;                                                       \
    cpa16(&As[BUF][arow * 40 + acol], adjA + (long)arow * cNC + kk_ + acol);    \
    cpa16(&Bs[BUF][arow * 40 + acol], HTb + (long)arow * cF + kk_ + acol);      \
    cpa16(&Bs[BUF][(arow + 128) * 40 + acol],                                   \
          HTb + (long)(arow + 128) * cF + kk_ + acol);                          \
    asm volatile("cp.async.commit_group;");                                     \
} while (0)

        LOAD1(0, 0);
        for (int kb = 0; kb < 8; kb++) {
            asm volatile("cp.async.wait_group 0;" ::: "memory");
            __syncthreads();
            if (kb + 1 < 8) LOAD1(kb + 1, (kb + 1) & 1);
            COMPUTE_SLAB(aBase[kb & 1], bBase[kb & 1]);
        }
#undef LOAD1

#pragma unroll
        for (int mi = 0; mi < 4; mi++) {
            int r0 = wm + mi * 16 + g;
#pragma unroll
            for (int ni = 0; ni < 4; ni++) {
                int c0 = wn + ni * 8 + tg * 2;
                __half* chp = AH + (c0 >> 5) * FS_A + (c0 & 31);
                *(__half2*)&chp[r0 * 40] =
                    __floats2half2_rn(acc[mi][ni][0], acc[mi][ni][1]);
                *(__half2*)&chp[(r0 + 8) * 40] =
                    __floats2half2_rn(acc[mi][ni][2], acc[mi][ni][3]);
                acc[mi][ni][0] = acc[mi][ni][1] = acc[mi][ni][2] = acc[mi][ni][3] = 0.f;
            }
        }
        __syncthreads();
    }

    const int nkb2 = compact ? 16 : 8;

#define LOAD2(KBI, BUF) do {                                                    \
    int kk_ = ((KBI) & 7) * 32;                                                 \
    if ((KBI) < 8)                                                              \
        cpa16(&As[BUF][arow * 40 + acol], Hrow + (long)arow * cF + kk_ + acol); \
    const __half* Wt_ = ((KBI) < 8) ? g_WT[0] : g_WT[1];                        \
    cpa16(&Bs[BUF][arow * 40 + acol], Wt_ + (long)arow * cF + kk_ + acol);      \
    cpa16(&Bs[BUF][(arow + 128) * 40 + acol],                                   \
          Wt_ + (long)(arow + 128) * cF + kk_ + acol);                          \
    asm volatile("cp.async.commit_group;");                                     \
} while (0)

    LOAD2(0, 0);
    for (int kb = 0; kb < nkb2; kb++) {
        asm volatile("cp.async.wait_group 0;" ::: "memory");
        __syncthreads();
        if (kb + 1 < nkb2) LOAD2(kb + 1, (kb + 1) & 1);
        unsigned aB = (kb < 8) ? aBase[kb & 1]
                               : (ahBase + (unsigned)(kb - 8) * (FS_A * 2));
        COMPUTE_SLAB(aB, bBase[kb & 1]);
    }
#undef LOAD2

    __half* Dh = g_h1 + (long)bx * 128 * cF;
#pragma unroll
    for (int mi = 0; mi < 4; mi++) {
        int r0 = wm + mi * 16 + g;
#pragma unroll
        for (int ni = 0; ni < 4; ni++) {
            int c0 = wn + ni * 8 + tg * 2;
            *(__half2*)&Dh[(long)r0 * cF + c0] = __floats2half2_rn(
                fast_tanh(acc[mi][ni][0]), fast_tanh(acc[mi][ni][1]));
            *(__half2*)&Dh[(long)(r0 + 8) * cF + c0] = __floats2half2_rn(
                fast_tanh(acc[mi][ni][2]), fast_tanh(acc[mi][ni][3]));
        }
    }
}

// ---------------------------------------------------------------------------
// k_layer2: fused layer-2 per batch (128 CTAs, 256 threads).
// Phase A: aggpack — ag2[r] = Adj[row_r,:] @ h1, F = [F1 | ag2] into smem.
// Phase B: mx = tanh(F @ [Ws2;Wm2])  (M=16, N=256, K=512) via warp MMA.
// ---------------------------------------------------------------------------
__global__ __launch_bounds__(256, 1) void k_layer2(const int* __restrict__ T,
                                                   float* __restrict__ out_mx) {
    extern __shared__ char smraw[];
    float*  adj_sm = (float*)smraw;                       // [16][256]
    __half* F_sm   = (__half*)(smraw + L2_ADJ);           // 16 chunks of [16][40]
    __half* Bs[2]  = { (__half*)(smraw + L2_ADJ + L2_F),
                       (__half*)(smraw + L2_ADJ + L2_F) + FS_B };

    const int b = blockIdx.x;
    const int tid = threadIdx.x, warp = tid >> 5, lane = tid & 31;
    const int g = lane >> 2, tg = lane & 3;
    const int Tb = T[b];

    unsigned fBase = (unsigned)__cvta_generic_to_shared(F_sm);
    unsigned bsBase[2] = { (unsigned)__cvta_generic_to_shared(Bs[0]),
                           (unsigned)__cvta_generic_to_shared(Bs[1]) };

    // prefetch B stage 0 (Ws2^T cols 0..31) — hides under phase A
#define LOADW(KBI, BUF) do {                                                    \
    const __half* Wt_ = ((KBI) < 8) ? g_WT[2] : g_WT[3];                        \
    int kk_ = ((KBI) & 7) * 32;                                                 \
    _Pragma("unroll")                                                           \
    for (int i = 0; i < 4; i++) {                                               \
        int u = tid * 4 + i;                                                    \
        int rw = u >> 2, cw = (u & 3) * 8;                                      \
        cpa16(&Bs[BUF][rw * 40 + cw], Wt_ + (long)rw * cF + kk_ + cw);          \
    }                                                                           \
    asm volatile("cp.async.commit_group;");                                     \
} while (0)

    LOADW(0, 0);

    // ---- phase A: aggpack ----
    {
        const int c = tid;
#pragma unroll
        for (int r = 0; r < cT; r++) {
            int row = Tb + r;
            adj_sm[r * cNC + c] = (row < cNC)
                ? __half2float(g_adjh[((long)b * cNC + row) * cNC + c]) : 0.f;
        }
        __syncthreads();

        float acc2[cT];
#pragma unroll
        for (int r = 0; r < cT; r++) acc2[r] = 0.f;

        const __half* h1b = g_h1 + (long)b * cNC * cF;
#pragma unroll 4
        for (int s = 0; s < cNC; s++) {
            float v = __half2float(h1b[(long)s * cF + c]);
#pragma unroll
            for (int r = 0; r < cT; r++) acc2[r] += adj_sm[r * cNC + s] * v;
        }

        const int ch = c >> 5, cc = c & 31;
#pragma unroll
        for (int r = 0; r < cT; r++) {
            int row = Tb + r;
            __half f1 = (row < cNC) ? g_h1[((long)b * cNC + row) * cF + c]
                                    : g_h1[((long)M1 + b * cT + r) * cF + c];
            F_sm[ch * (cT * 40) + r * 40 + cc] = f1;                       // K seg 0
            F_sm[(8 + ch) * (cT * 40) + r * 40 + cc] = __float2half(acc2[r]); // K seg 1
        }
    }
    __syncthreads();

    // ---- phase B: 16x256x512 GEMM ----
    const int wn = warp * 32;
    const int aoffA = ((lane & 15) * 40 + (lane >> 4) * 8) * 2;
    int boff[2];
    {
        int q = lane >> 3, r = lane & 7;
#pragma unroll
        for (int pi = 0; pi < 2; pi++)
            boff[pi] = ((wn + pi * 16 + (q >> 1) * 8 + r) * 40 + (q & 1) * 8) * 2;
    }

    float acc[4][4];
#pragma unroll
    for (int a = 0; a < 4; a++)
#pragma unroll
        for (int c = 0; c < 4; c++) acc[a][c] = 0.f;

    for (int kb = 0; kb < 16; kb++) {
        asm volatile("cp.async.wait_group 0;" ::: "memory");
        __syncthreads();
        if (kb + 1 < 16) LOADW(kb + 1, (kb + 1) & 1);
        const unsigned bB = bsBase[kb & 1];
        const unsigned aB = fBase + (unsigned)kb * (cT * 40 * 2);

#pragma unroll
        for (int ks = 0; ks < 2; ks++) {
            unsigned af[4], bf[2][4];
            LDSM4(af, aB + aoffA + ks * 32);
#pragma unroll
            for (int pi = 0; pi < 2; pi++) LDSM4(bf[pi], bB + boff[pi] + ks * 32);
#pragma unroll
            for (int ni = 0; ni < 4; ni++)
                MMA16(acc[ni], af,
                      bf[ni >> 1][(ni & 1) * 2], bf[ni >> 1][(ni & 1) * 2 + 1]);
        }
    }
#undef LOADW

    float* Db = out_mx + (long)b * cT * cF;
#pragma unroll
    for (int ni = 0; ni < 4; ni++) {
        int c0 = wn + ni * 8 + tg * 2;
        Db[(long)g * cF + c0]           = fast_tanh(acc[ni][0]);
        Db[(long)g * cF + c0 + 1]       = fast_tanh(acc[ni][1]);
        Db[(long)(g + 8) * cF + c0]     = fast_tanh(acc[ni][2]);
        Db[(long)(g + 8) * cF + c0 + 1] = fast_tanh(acc[ni][3]);
    }
}

// ---------------------------------------------------------------------------
// staging / passthrough kernels (R13-proven)
// ---------------------------------------------------------------------------
__global__ void k_nodes_compactT(const float* __restrict__ nodes, const float* __restrict__ x,
                                 const int* __restrict__ T, float* __restrict__ out_nn) {
    __shared__ __half t[32][33];
    int b = blockIdx.z;
    int x0 = blockIdx.x * 32, y0 = blockIdx.y * 32;
    int tx = threadIdx.x, ty = threadIdx.y;
    int Tb = T[b];
#pragma unroll
    for (int i = 0; i < 4; i++) {
        int n = y0 + ty + i * 8;
        int d = n - Tb;
        float v = (d >= 0 && d < cT) ? x[((long)b * cT + d) * cF + x0 + tx]
                                     : nodes[((long)b * cN + n) * cF + x0 + tx];
        out_nn[((long)b * cN + n) * cF + x0 + tx] = v;
        __half h = __float2half(v);
        g_H[((long)b * cNC + n) * cF + x0 + tx] = h;
        t[ty + i * 8][tx] = h;
    }
    __syncthreads();
#pragma unroll
    for (int i = 0; i < 4; i++)
        g_HT[((long)b * cNC + x0 + ty + i * 8) * cF + y0 + tx] = t[tx][ty + i * 8];
}

__global__ void k_nodes_rest(const float4* __restrict__ x, const float4* __restrict__ nodes,
                             const int* __restrict__ T, float4* __restrict__ out_nn) {
    const long total = (long)cB * (cN - cNC) * 64;
    for (long idx = blockIdx.x * (long)blockDim.x + threadIdx.x; idx < total;
         idx += (long)gridDim.x * blockDim.x) {
        int b   = (int)(idx / ((cN - cNC) * 64));
        int rem = (int)(idx - (long)b * ((cN - cNC) * 64));
        int n = cNC + (rem >> 6), q = rem & 63;
        int d = n - T[b];
        long o = ((long)b * cN + n) * 64 + q;
        out_nn[o] = (d >= 0 && d < cT) ? x[((long)b * cT + d) * 64 + q] : nodes[o];
    }
}

__global__ void k_castx(const float2* __restrict__ x) {
    const long total = (long)MX * cF / 2;
    for (long i = blockIdx.x * (long)blockDim.x + threadIdx.x; i < total;
         i += (long)gridDim.x * blockDim.x) {
        float2 v = x[i];
        *(__half2*)&g_H[(long)M1 * cF + i * 2] = __floats2half2_rn(v.x, v.y);
    }
}

__global__ void k_zero4(float4* p, long n4) {
    for (long i = blockIdx.x * (long)blockDim.x + threadIdx.x; i < n4;
         i += (long)gridDim.x * blockDim.x)
        p[i] = make_float4(0.f, 0.f, 0.f, 0.f);
}

// Fused edge pass: out_ed/out_wt/out_tt passthrough + half adjacency atomics
__global__ void k_edges_fused(const int* __restrict__ edges, const float* __restrict__ w,
                              const int* __restrict__ T, const int* __restrict__ taus,
                              float* __restrict__ out_ed, float* __restrict__ out_wt,
                              float* __restrict__ out_tt) {
    if (blockIdx.x == 0 && threadIdx.x < cB)
        out_tt[threadIdx.x] = (float)(T[threadIdx.x] + taus[threadIdx.x]);
    const int total = cB * cE;
    for (int i = blockIdx.x * blockDim.x + threadIdx.x; i < total; i += gridDim.x * blockDim.x) {
        int b = i / cE, e = i - b * cE;
        int s = edges[(long)b * 2 * cE + e];
        int d = edges[(long)b * 2 * cE + cE + e];
        float wv = w[i];
        out_ed[(long)b * 2 * cE + e]      = (float)s;
        out_ed[(long)b * 2 * cE + cE + e] = (float)d;
        out_wt[i] = wv;
        if (s >= 0 && d >= 0 && s < cNC && d < cNC)
            atomicAdd(&g_adjh[((long)b * cNC + d) * cNC + s], __float2half(wv));
    }
}

__global__ void k_packWT(const float* __restrict__ W0, const float* __restrict__ W1,
                         const float* __restrict__ W2, const float* __restrict__ W3) {
    __shared__ float t[32][33];
    const float* Ws[4] = {W0, W1, W2, W3};
    int z = blockIdx.z;
    int x0 = blockIdx.x * 32, y0 = blockIdx.y * 32;
    int tx = threadIdx.x, ty = threadIdx.y;
#pragma unroll
    for (int i = 0; i < 4; i++)
        t[ty + i * 8][tx] = Ws[z][(y0 + ty + i * 8) * cF + x0 + tx];
    __syncthreads();
#pragma unroll
    for (int i = 0; i < 4; i++)
        g_WT[z][(x0 + ty + i * 8) * cF + y0 + tx] = __float2half(t[tx][ty + i * 8]);
}

// ---------------------------------------------------------------------------
// Launcher
// ---------------------------------------------------------------------------
extern "C" void kernel_launch(void* const* d_in, const int* in_sizes, int n_in,
                              void* d_out, int out_size) {
    const float* x       = (const float*)d_in[0];
    const int*   taus    = (const int*)  d_in[1];
    const float* nodes   = (const float*)d_in[2];
    const int*   edges   = (const int*)  d_in[3];
    const float* weights = (const float*)d_in[4];
    const int*   T       = (const int*)  d_in[5];
    const float* Ws1     = (const float*)d_in[6];
    const float* Wm1     = (const float*)d_in[7];
    const float* Ws2     = (const float*)d_in[8];
    const float* Wm2     = (const float*)d_in[9];

    float* out    = (float*)d_out;
    float* out_mx = out + OFF_MX;
    float* out_nn = out + OFF_NN;
    float* out_ed = out + OFF_ED;
    float* out_wt = out + OFF_WT;
    float* out_tt = out + OFF_TT;

    __half *p_adjh;
    cudaGetSymbolAddress((void**)&p_adjh, g_adjh);

    static cudaStream_t s1 = nullptr, s2 = nullptr, s3 = nullptr;
    static cudaEvent_t evF = nullptr, ev1 = nullptr, evX = nullptr, evW = nullptr;
    if (!s1) {
        cudaStreamCreateWithFlags(&s1, cudaStreamNonBlocking);
        cudaStreamCreateWithFlags(&s2, cudaStreamNonBlocking);
        cudaStreamCreateWithFlags(&s3, cudaStreamNonBlocking);
        cudaEventCreateWithFlags(&evF, cudaEventDisableTiming);
        cudaEventCreateWithFlags(&ev1, cudaEventDisableTiming);
        cudaEventCreateWithFlags(&evX, cudaEventDisableTiming);
        cudaEventCreateWithFlags(&evW, cudaEventDisableTiming);
        cudaFuncSetAttribute(k_layer1, cudaFuncAttributeMaxDynamicSharedMemorySize, FSMEM_BYTES);
        cudaFuncSetAttribute(k_layer2, cudaFuncAttributeMaxDynamicSharedMemorySize, L2SMEM_BYTES);
    }

    // fork
    cudaEventRecord(evF, 0);
    cudaStreamWaitEvent(s1, evF, 0);
    cudaStreamWaitEvent(s2, evF, 0);
    cudaStreamWaitEvent(s3, evF, 0);

    // s1: bulk passthrough (DRAM-bound, overlaps all compute)
    k_nodes_rest<<<4096, 256, 0, s1>>>((const float4*)x, (const float4*)nodes, T,
                                       (float4*)out_nn);
    cudaEventRecord(ev1, s1);

    // s2: compact nodes (out_nn + H + HT)
    k_nodes_compactT<<<dim3(8, 8, cB), dim3(32, 8), 0, s2>>>(nodes, x, T, out_nn);
    cudaEventRecord(evX, s2);

    // s3: X rows of H + packed weights (independent of s2)
    k_castx<<<512, 256, 0, s3>>>((const float2*)x);
    k_packWT<<<dim3(8, 8, 4), dim3(32, 8), 0, s3>>>(Ws1, Wm1, Ws2, Wm2);
    cudaEventRecord(evW, s3);

    // main: adjacency (half atomics) fused with edges/weights/tt passthrough
    k_zero4<<<1024, 256>>>((float4*)p_adjh, (long)cB * cNC * cNC / 8);
    k_edges_fused<<<2048, 256>>>(edges, weights, T, taus, out_ed, out_wt, out_tt);
    cudaStreamWaitEvent(0, evX, 0);
    cudaStreamWaitEvent(0, evW, 0);

    // fused layer 1: AH (smem) + h1 = tanh(H@Ws1 + AH@Wm1), one launch
    k_layer1<<<MEXT / 128, 512, FSMEM_BYTES>>>();

    // fused layer 2: aggpack + 16x256x512 GEMM + tanh -> out_mx, one launch
    k_layer2<<<cB, 256, L2SMEM_BYTES>>>(T, out_mx);

    // join passthrough branch
    cudaStreamWaitEvent(0, ev1, 0);
}